// round 11
// baseline (speedup 1.0000x reference)
#include <cuda_runtime.h>
#include <math.h>

// ---------------------------------------------------------------------------
// MultiHeadAttention: out = softmax((qWq^T+bq)(kWk^T+bk)^T / 8) (vWv^T+bv) Wo^T + bo
// B=4, H=8, S=2048, D=512, hd=64. Mask is a no-op in the reference.
// fp32 CUDA-core path, 8x8 micro-tiles.
// ---------------------------------------------------------------------------

#define NB   4
#define NH   8
#define SEQ  2048
#define DM   512
#define HD   64
#define MROWS (NB * SEQ)   // 8192

// Scratch (allocation-free rule -> __device__ globals). 4 x 16MB = 64MB.
__device__ float g_Q[NB * NH * SEQ * HD];   // [B,H,S,hd]
__device__ float g_K[NB * NH * SEQ * HD];
__device__ float g_V[NB * NH * SEQ * HD];
__device__ float g_A[NB * SEQ * DM];        // attention output, [B,S,D]

__device__ __forceinline__ float ex2(float x) {
    float r;
    asm("ex2.approx.ftz.f32 %0, %1;" : "=f"(r) : "f"(x));
    return r;
}

// ---------------------------------------------------------------------------
// NT GEMM: C[m,n] = sum_k X[m,k] * W[n,k] + bias[n]
// M=8192, N=512, K=512. Tiles: BM=128, BN=128, BK=16. 256 threads, 8x8 micro.
// Global loads for chunk k+1 are issued before computing chunk k (reg prefetch).
// MODE 0/1/2: write head-split into g_Q/g_K/g_V. MODE 3: X:=g_A, write [M,N].
// ---------------------------------------------------------------------------
template <int MODE>
__global__ __launch_bounds__(256)
void proj_kernel(const float* __restrict__ X,
                 const float* __restrict__ W,
                 const float* __restrict__ bias,
                 float* __restrict__ ext_out)
{
    constexpr int BK = 16;
    __shared__ __align__(16) float As[BK][128 + 4];
    __shared__ __align__(16) float Bs[BK][128 + 4];

    const float* Xin = (MODE == 3) ? g_A : X;

    const int tid = threadIdx.x;        // 0..255
    const int tx  = tid & 15;           // 8 cols each (BN=128)
    const int ty  = tid >> 4;           // 8 rows each (BM=128)
    const int m0  = blockIdx.y * 128;
    const int n0  = blockIdx.x * 128;

    const int lr = tid >> 2;            // 0..63
    const int lc = (tid & 3) * 4;       // 0,4,8,12

    const float* Ap0 = Xin + (size_t)(m0 + lr) * DM + lc;
    const float* Ap1 = Ap0 + (size_t)64 * DM;
    const float* Bp0 = W   + (size_t)(n0 + lr) * DM + lc;
    const float* Bp1 = Bp0 + (size_t)64 * DM;

    float acc[8][8];
#pragma unroll
    for (int i = 0; i < 8; i++)
#pragma unroll
        for (int j = 0; j < 8; j++) acc[i][j] = 0.f;

    // prefetch chunk 0
    float4 ra0 = *(const float4*)(Ap0);
    float4 ra1 = *(const float4*)(Ap1);
    float4 rb0 = *(const float4*)(Bp0);
    float4 rb1 = *(const float4*)(Bp1);

    for (int k0 = 0; k0 < DM; k0 += BK) {
        __syncthreads();
        As[lc + 0][lr]      = ra0.x; As[lc + 1][lr]      = ra0.y;
        As[lc + 2][lr]      = ra0.z; As[lc + 3][lr]      = ra0.w;
        As[lc + 0][lr + 64] = ra1.x; As[lc + 1][lr + 64] = ra1.y;
        As[lc + 2][lr + 64] = ra1.z; As[lc + 3][lr + 64] = ra1.w;
        Bs[lc + 0][lr]      = rb0.x; Bs[lc + 1][lr]      = rb0.y;
        Bs[lc + 2][lr]      = rb0.z; Bs[lc + 3][lr]      = rb0.w;
        Bs[lc + 0][lr + 64] = rb1.x; Bs[lc + 1][lr + 64] = rb1.y;
        Bs[lc + 2][lr + 64] = rb1.z; Bs[lc + 3][lr + 64] = rb1.w;
        __syncthreads();

        if (k0 + BK < DM) {             // issue next chunk's loads early
            ra0 = *(const float4*)(Ap0 + k0 + BK);
            ra1 = *(const float4*)(Ap1 + k0 + BK);
            rb0 = *(const float4*)(Bp0 + k0 + BK);
            rb1 = *(const float4*)(Bp1 + k0 + BK);
        }

#pragma unroll
        for (int kk = 0; kk < BK; kk++) {
            float4 av0 = *(const float4*)&As[kk][ty * 8];
            float4 av1 = *(const float4*)&As[kk][ty * 8 + 4];
            float4 bv0 = *(const float4*)&Bs[kk][tx * 8];
            float4 bv1 = *(const float4*)&Bs[kk][tx * 8 + 4];
            float a[8] = {av0.x, av0.y, av0.z, av0.w, av1.x, av1.y, av1.z, av1.w};
            float b[8] = {bv0.x, bv0.y, bv0.z, bv0.w, bv1.x, bv1.y, bv1.z, bv1.w};
#pragma unroll
            for (int i = 0; i < 8; i++)
#pragma unroll
                for (int j = 0; j < 8; j++)
                    acc[i][j] = fmaf(a[i], b[j], acc[i][j]);
        }
    }

    const int col = n0 + tx * 8;
    float4 bb0 = *(const float4*)&bias[col];
    float4 bb1 = *(const float4*)&bias[col + 4];
    float bb[8] = {bb0.x, bb0.y, bb0.z, bb0.w, bb1.x, bb1.y, bb1.z, bb1.w};

    float* outp;
    if (MODE == 0) outp = g_Q;
    else if (MODE == 1) outp = g_K;
    else if (MODE == 2) outp = g_V;
    else outp = ext_out;

#pragma unroll
    for (int i = 0; i < 8; i++) {
        const int m = m0 + ty * 8 + i;
        float4 v0, v1;
        v0.x = acc[i][0] + bb[0]; v0.y = acc[i][1] + bb[1];
        v0.z = acc[i][2] + bb[2]; v0.w = acc[i][3] + bb[3];
        v1.x = acc[i][4] + bb[4]; v1.y = acc[i][5] + bb[5];
        v1.z = acc[i][6] + bb[6]; v1.w = acc[i][7] + bb[7];
        if (MODE < 3) {
            const int b = m >> 11;          // / SEQ
            const int s = m & (SEQ - 1);
            const int h = col >> 6;         // / HD  (col is a multiple of 8; 8|64 so
            const int d = col & (HD - 1);   //  the 8-col group stays inside one head)
            float* p = &outp[(((size_t)(b * NH + h) * SEQ) + s) * HD + d];
            *(float4*)p       = v0;
            *(float4*)(p + 4) = v1;
        } else {
            float* p = &outp[(size_t)m * DM + col];
            *(float4*)p       = v0;
            *(float4*)(p + 4) = v1;
        }
    }
}

// ---------------------------------------------------------------------------
// Flash attention: per (b,h) x 128-query block, stream 64-key tiles.
// 128 threads, 8x8 micro-tiles. Q pre-scaled by 0.125*log2(e); softmax in
// base-2 domain via raw ex2.approx. P staged transposed in smem for PV.
// ---------------------------------------------------------------------------
__global__ __launch_bounds__(128, 2)
void flash_kernel()
{
    constexpr int BM = 128, BN = 64;
    constexpr int QS = BM + 4;   // 132
    constexpr int KS = BN + 4;   // 68
    constexpr int VS = HD + 4;   // 68
    constexpr int PS = BM + 4;   // 132
    constexpr float QSCALE = 0.125f * 1.4426950408889634f;  // /sqrt(64) * log2(e)

    extern __shared__ __align__(16) float sm[];
    float* Qs = sm;                     // [HD][QS]  transposed: Qs[d][r]
    float* Ks = Qs + HD * QS;           // [HD][KS]  transposed: Ks[d][t]
    float* Vs = Ks + HD * KS;           // [BN][VS]  natural:    Vs[t][d]
    float* Ps = Vs + BN * VS;           // [BN][PS]  transposed: Ps[t][r]

    const int tid = threadIdx.x;        // 0..127
    const int tx  = tid & 7;            // keys/dims: 8 groups of 8
    const int ty  = tid >> 3;           // rows: 16 groups of 8
    const int s0  = blockIdx.x * BM;
    const int bh  = blockIdx.y;         // b*NH + h

    const float* Qg = g_Q + (size_t)bh * SEQ * HD;
    const float* Kg = g_K + (size_t)bh * SEQ * HD;
    const float* Vg = g_V + (size_t)bh * SEQ * HD;

    const int lrow = tid >> 4;          // 0..7
    const int lcol = (tid & 15) * 4;    // 0..60

    // Load Q tile (scaled), transposed.
#pragma unroll
    for (int it = 0; it < 16; it++) {
        const int r = lrow + it * 8;    // 0..127
        float4 q = *(const float4*)&Qg[(size_t)(s0 + r) * HD + lcol];
        Qs[(lcol + 0) * QS + r] = q.x * QSCALE;
        Qs[(lcol + 1) * QS + r] = q.y * QSCALE;
        Qs[(lcol + 2) * QS + r] = q.z * QSCALE;
        Qs[(lcol + 3) * QS + r] = q.w * QSCALE;
    }

    float o[8][8];
    float mrow[8], lsum[8];
#pragma unroll
    for (int i = 0; i < 8; i++) {
        mrow[i] = -1e30f;
        lsum[i] = 0.f;
#pragma unroll
        for (int j = 0; j < 8; j++) o[i][j] = 0.f;
    }

    for (int kt = 0; kt < SEQ / BN; kt++) {
        const int t0 = kt * BN;
        __syncthreads();   // prior-iteration PV reads of Ks/Vs/Ps complete
#pragma unroll
        for (int it = 0; it < 8; it++) {
            const int r = lrow + it * 8;   // 0..63
            float4 kv = *(const float4*)&Kg[(size_t)(t0 + r) * HD + lcol];
            Ks[(lcol + 0) * KS + r] = kv.x;
            Ks[(lcol + 1) * KS + r] = kv.y;
            Ks[(lcol + 2) * KS + r] = kv.z;
            Ks[(lcol + 3) * KS + r] = kv.w;
            float4 vv = *(const float4*)&Vg[(size_t)(t0 + r) * HD + lcol];
            *(float4*)&Vs[r * VS + lcol] = vv;
        }
        __syncthreads();

        // S = Qs^T Ks : 128 rows x 64 keys, reduction over HD=64
        float s[8][8];
#pragma unroll
        for (int i = 0; i < 8; i++)
#pragma unroll
            for (int j = 0; j < 8; j++) s[i][j] = 0.f;

#pragma unroll 4
        for (int d = 0; d < HD; d++) {
            float4 av0 = *(const float4*)&Qs[d * QS + ty * 8];
            float4 av1 = *(const float4*)&Qs[d * QS + ty * 8 + 4];
            float4 bv0 = *(const float4*)&Ks[d * KS + tx * 8];
            float4 bv1 = *(const float4*)&Ks[d * KS + tx * 8 + 4];
            float a[8] = {av0.x, av0.y, av0.z, av0.w, av1.x, av1.y, av1.z, av1.w};
            float b[8] = {bv0.x, bv0.y, bv0.z, bv0.w, bv1.x, bv1.y, bv1.z, bv1.w};
#pragma unroll
            for (int i = 0; i < 8; i++)
#pragma unroll
                for (int j = 0; j < 8; j++)
                    s[i][j] = fmaf(a[i], b[j], s[i][j]);
        }

        // Online softmax (base-2). Row reduction across the 8-thread tx group.
#pragma unroll
        for (int i = 0; i < 8; i++) {
            float mx = s[i][0];
#pragma unroll
            for (int j = 1; j < 8; j++) mx = fmaxf(mx, s[i][j]);
#pragma unroll
            for (int off = 4; off > 0; off >>= 1)
                mx = fmaxf(mx, __shfl_xor_sync(0xffffffffu, mx, off, 8));
            const float mnew = fmaxf(mrow[i], mx);
            const float corr = ex2(mrow[i] - mnew);
            float ps = 0.f;
#pragma unroll
            for (int j = 0; j < 8; j++) {
                const float p = ex2(s[i][j] - mnew);
                ps += p;
                s[i][j] = p;
            }
#pragma unroll
            for (int off = 4; off > 0; off >>= 1)
                ps += __shfl_xor_sync(0xffffffffu, ps, off, 8);
            lsum[i] = lsum[i] * corr + ps;
            mrow[i] = mnew;
#pragma unroll
            for (int j = 0; j < 8; j++) o[i][j] *= corr;
        }

        // Stage P transposed: Ps[key][row], float4 over rows.
#pragma unroll
        for (int j = 0; j < 8; j++) {
            float* p = &Ps[(tx * 8 + j) * PS + ty * 8];
            *(float4*)p       = make_float4(s[0][j], s[1][j], s[2][j], s[3][j]);
            *(float4*)(p + 4) = make_float4(s[4][j], s[5][j], s[6][j], s[7][j]);
        }
        __syncthreads();

        // O += P V : 128 rows x 64 dims, reduction over 64 keys
#pragma unroll 4
        for (int t = 0; t < BN; t++) {
            float4 pv0 = *(const float4*)&Ps[t * PS + ty * 8];
            float4 pv1 = *(const float4*)&Ps[t * PS + ty * 8 + 4];
            float4 vv0 = *(const float4*)&Vs[t * VS + tx * 8];
            float4 vv1 = *(const float4*)&Vs[t * VS + tx * 8 + 4];
            float p[8] = {pv0.x, pv0.y, pv0.z, pv0.w, pv1.x, pv1.y, pv1.z, pv1.w};
            float vb[8] = {vv0.x, vv0.y, vv0.z, vv0.w, vv1.x, vv1.y, vv1.z, vv1.w};
#pragma unroll
            for (int i = 0; i < 8; i++)
#pragma unroll
                for (int j = 0; j < 8; j++)
                    o[i][j] = fmaf(p[i], vb[j], o[i][j]);
        }
    }

    // Epilogue: normalize, write to [B,S,D] (re-interleave heads).
    const int b = bh >> 3;
    const int h = bh & (NH - 1);
#pragma unroll
    for (int i = 0; i < 8; i++) {
        const float inv = 1.0f / lsum[i];
        const int srow = s0 + ty * 8 + i;
        float* p = &g_A[((size_t)(b * SEQ) + srow) * DM + h * HD + tx * 8];
        *(float4*)p       = make_float4(o[i][0] * inv, o[i][1] * inv,
                                        o[i][2] * inv, o[i][3] * inv);
        *(float4*)(p + 4) = make_float4(o[i][4] * inv, o[i][5] * inv,
                                        o[i][6] * inv, o[i][7] * inv);
    }
}

// ---------------------------------------------------------------------------
// kernel_launch: 5 launches, default stream, graph-capturable.
// Input order: q,k,v,mask,Wq,bq,Wk,bk,Wv,bv,Wo,bo
// ---------------------------------------------------------------------------
extern "C" void kernel_launch(void* const* d_in, const int* in_sizes, int n_in,
                              void* d_out, int out_size)
{
    (void)in_sizes; (void)n_in; (void)out_size;
    const float* q  = (const float*)d_in[0];
    const float* k  = (const float*)d_in[1];
    const float* v  = (const float*)d_in[2];
    // d_in[3] = mask (int32) — a no-op in the reference math
    const float* Wq = (const float*)d_in[4];
    const float* bq = (const float*)d_in[5];
    const float* Wk = (const float*)d_in[6];
    const float* bk = (const float*)d_in[7];
    const float* Wv = (const float*)d_in[8];
    const float* bv = (const float*)d_in[9];
    const float* Wo = (const float*)d_in[10];
    const float* bo = (const float*)d_in[11];
    float* out = (float*)d_out;

    const dim3 pgrid(DM / 128, MROWS / 128);   // (4, 64)

    proj_kernel<0><<<pgrid, 256>>>(q, Wq, bq, nullptr);
    proj_kernel<1><<<pgrid, 256>>>(k, Wk, bk, nullptr);
    proj_kernel<2><<<pgrid, 256>>>(v, Wv, bv, nullptr);

    const int smem_bytes = (HD * (128 + 4) + HD * (64 + 4) +
                            64 * (HD + 4) + 64 * (128 + 4)) * (int)sizeof(float); // 102400
    cudaFuncSetAttribute(flash_kernel,
                         cudaFuncAttributeMaxDynamicSharedMemorySize, smem_bytes);
    flash_kernel<<<dim3(SEQ / 128, NB * NH), 128, smem_bytes>>>();

    proj_kernel<3><<<pgrid, 256>>>(nullptr, Wo, bo, out);
}

// round 12
// speedup vs baseline: 1.0025x; 1.0025x over previous
#include <cuda_runtime.h>
#include <math.h>

// ---------------------------------------------------------------------------
// MultiHeadAttention: out = softmax((qWq^T+bq)(kWk^T+bk)^T / 8) (vWv^T+bv) Wo^T + bo
// B=4, H=8, S=2048, D=512, hd=64. Mask is a no-op in the reference.
// fp32 CUDA-core path, 8x8 micro-tiles.
// ---------------------------------------------------------------------------

#define NB   4
#define NH   8
#define SEQ  2048
#define DM   512
#define HD   64
#define MROWS (NB * SEQ)   // 8192

// Scratch (allocation-free rule -> __device__ globals). 4 x 16MB = 64MB.
__device__ float g_Q[NB * NH * SEQ * HD];   // [B,H,S,hd]
__device__ float g_K[NB * NH * SEQ * HD];
__device__ float g_V[NB * NH * SEQ * HD];
__device__ float g_A[NB * SEQ * DM];        // attention output, [B,S,D]

__device__ __forceinline__ float ex2(float x) {
    float r;
    asm("ex2.approx.ftz.f32 %0, %1;" : "=f"(r) : "f"(x));
    return r;
}

// ---------------------------------------------------------------------------
// NT GEMM: C[m,n] = sum_k X[m,k] * W[n,k] + bias[n]
// M=8192, N=512, K=512. Tiles: BM=128, BN=128, BK=16. 256 threads, 8x8 micro.
// Global loads for chunk k+1 are issued before computing chunk k (reg prefetch).
// MODE 0/1/2: write head-split into g_Q/g_K/g_V. MODE 3: X:=g_A, write [M,N].
// ---------------------------------------------------------------------------
template <int MODE>
__global__ __launch_bounds__(256)
void proj_kernel(const float* __restrict__ X,
                 const float* __restrict__ W,
                 const float* __restrict__ bias,
                 float* __restrict__ ext_out)
{
    constexpr int BK = 16;
    __shared__ __align__(16) float As[BK][128 + 4];
    __shared__ __align__(16) float Bs[BK][128 + 4];

    const float* Xin = (MODE == 3) ? g_A : X;

    const int tid = threadIdx.x;        // 0..255
    const int tx  = tid & 15;           // 8 cols each (BN=128)
    const int ty  = tid >> 4;           // 8 rows each (BM=128)
    const int m0  = blockIdx.y * 128;
    const int n0  = blockIdx.x * 128;

    const int lr = tid >> 2;            // 0..63
    const int lc = (tid & 3) * 4;       // 0,4,8,12

    const float* Ap0 = Xin + (size_t)(m0 + lr) * DM + lc;
    const float* Ap1 = Ap0 + (size_t)64 * DM;
    const float* Bp0 = W   + (size_t)(n0 + lr) * DM + lc;
    const float* Bp1 = Bp0 + (size_t)64 * DM;

    float acc[8][8];
#pragma unroll
    for (int i = 0; i < 8; i++)
#pragma unroll
        for (int j = 0; j < 8; j++) acc[i][j] = 0.f;

    // prefetch chunk 0
    float4 ra0 = *(const float4*)(Ap0);
    float4 ra1 = *(const float4*)(Ap1);
    float4 rb0 = *(const float4*)(Bp0);
    float4 rb1 = *(const float4*)(Bp1);

    for (int k0 = 0; k0 < DM; k0 += BK) {
        __syncthreads();
        As[lc + 0][lr]      = ra0.x; As[lc + 1][lr]      = ra0.y;
        As[lc + 2][lr]      = ra0.z; As[lc + 3][lr]      = ra0.w;
        As[lc + 0][lr + 64] = ra1.x; As[lc + 1][lr + 64] = ra1.y;
        As[lc + 2][lr + 64] = ra1.z; As[lc + 3][lr + 64] = ra1.w;
        Bs[lc + 0][lr]      = rb0.x; Bs[lc + 1][lr]      = rb0.y;
        Bs[lc + 2][lr]      = rb0.z; Bs[lc + 3][lr]      = rb0.w;
        Bs[lc + 0][lr + 64] = rb1.x; Bs[lc + 1][lr + 64] = rb1.y;
        Bs[lc + 2][lr + 64] = rb1.z; Bs[lc + 3][lr + 64] = rb1.w;
        __syncthreads();

        if (k0 + BK < DM) {             // issue next chunk's loads early
            ra0 = *(const float4*)(Ap0 + k0 + BK);
            ra1 = *(const float4*)(Ap1 + k0 + BK);
            rb0 = *(const float4*)(Bp0 + k0 + BK);
            rb1 = *(const float4*)(Bp1 + k0 + BK);
        }

#pragma unroll
        for (int kk = 0; kk < BK; kk++) {
            float4 av0 = *(const float4*)&As[kk][ty * 8];
            float4 av1 = *(const float4*)&As[kk][ty * 8 + 4];
            float4 bv0 = *(const float4*)&Bs[kk][tx * 8];
            float4 bv1 = *(const float4*)&Bs[kk][tx * 8 + 4];
            float a[8] = {av0.x, av0.y, av0.z, av0.w, av1.x, av1.y, av1.z, av1.w};
            float b[8] = {bv0.x, bv0.y, bv0.z, bv0.w, bv1.x, bv1.y, bv1.z, bv1.w};
#pragma unroll
            for (int i = 0; i < 8; i++)
#pragma unroll
                for (int j = 0; j < 8; j++)
                    acc[i][j] = fmaf(a[i], b[j], acc[i][j]);
        }
    }

    const int col = n0 + tx * 8;
    float4 bb0 = *(const float4*)&bias[col];
    float4 bb1 = *(const float4*)&bias[col + 4];
    float bb[8] = {bb0.x, bb0.y, bb0.z, bb0.w, bb1.x, bb1.y, bb1.z, bb1.w};

    float* outp;
    if (MODE == 0) outp = g_Q;
    else if (MODE == 1) outp = g_K;
    else if (MODE == 2) outp = g_V;
    else outp = ext_out;

#pragma unroll
    for (int i = 0; i < 8; i++) {
        const int m = m0 + ty * 8 + i;
        float4 v0, v1;
        v0.x = acc[i][0] + bb[0]; v0.y = acc[i][1] + bb[1];
        v0.z = acc[i][2] + bb[2]; v0.w = acc[i][3] + bb[3];
        v1.x = acc[i][4] + bb[4]; v1.y = acc[i][5] + bb[5];
        v1.z = acc[i][6] + bb[6]; v1.w = acc[i][7] + bb[7];
        if (MODE < 3) {
            const int b = m >> 11;          // / SEQ
            const int s = m & (SEQ - 1);
            const int h = col >> 6;         // / HD  (col is a multiple of 8; 8|64 so
            const int d = col & (HD - 1);   //  the 8-col group stays inside one head)
            float* p = &outp[(((size_t)(b * NH + h) * SEQ) + s) * HD + d];
            *(float4*)p       = v0;
            *(float4*)(p + 4) = v1;
        } else {
            float* p = &outp[(size_t)m * DM + col];
            *(float4*)p       = v0;
            *(float4*)(p + 4) = v1;
        }
    }
}

// ---------------------------------------------------------------------------
// Flash attention: per (b,h) x 128-query block, stream 64-key tiles.
// 128 threads, 8x8 micro-tiles. Q pre-scaled by 0.125*log2(e); softmax in
// base-2 domain via raw ex2.approx. P staged transposed in smem for PV.
// ---------------------------------------------------------------------------
__global__ __launch_bounds__(128, 2)
void flash_kernel()
{
    constexpr int BM = 128, BN = 64;
    constexpr int QS = BM + 4;   // 132
    constexpr int KS = BN + 4;   // 68
    constexpr int VS = HD + 4;   // 68
    constexpr int PS = BM + 4;   // 132
    constexpr float QSCALE = 0.125f * 1.4426950408889634f;  // /sqrt(64) * log2(e)

    extern __shared__ __align__(16) float sm[];
    float* Qs = sm;                     // [HD][QS]  transposed: Qs[d][r]
    float* Ks = Qs + HD * QS;           // [HD][KS]  transposed: Ks[d][t]
    float* Vs = Ks + HD * KS;           // [BN][VS]  natural:    Vs[t][d]
    float* Ps = Vs + BN * VS;           // [BN][PS]  transposed: Ps[t][r]

    const int tid = threadIdx.x;        // 0..127
    const int tx  = tid & 7;            // keys/dims: 8 groups of 8
    const int ty  = tid >> 3;           // rows: 16 groups of 8
    const int s0  = blockIdx.x * BM;
    const int bh  = blockIdx.y;         // b*NH + h

    const float* Qg = g_Q + (size_t)bh * SEQ * HD;
    const float* Kg = g_K + (size_t)bh * SEQ * HD;
    const float* Vg = g_V + (size_t)bh * SEQ * HD;

    const int lrow = tid >> 4;          // 0..7
    const int lcol = (tid & 15) * 4;    // 0..60

    // Load Q tile (scaled), transposed.
#pragma unroll
    for (int it = 0; it < 16; it++) {
        const int r = lrow + it * 8;    // 0..127
        float4 q = *(const float4*)&Qg[(size_t)(s0 + r) * HD + lcol];
        Qs[(lcol + 0) * QS + r] = q.x * QSCALE;
        Qs[(lcol + 1) * QS + r] = q.y * QSCALE;
        Qs[(lcol + 2) * QS + r] = q.z * QSCALE;
        Qs[(lcol + 3) * QS + r] = q.w * QSCALE;
    }

    float o[8][8];
    float mrow[8], lsum[8];
#pragma unroll
    for (int i = 0; i < 8; i++) {
        mrow[i] = -1e30f;
        lsum[i] = 0.f;
#pragma unroll
        for (int j = 0; j < 8; j++) o[i][j] = 0.f;
    }

    for (int kt = 0; kt < SEQ / BN; kt++) {
        const int t0 = kt * BN;
        __syncthreads();   // prior-iteration PV reads of Ks/Vs/Ps complete
#pragma unroll
        for (int it = 0; it < 8; it++) {
            const int r = lrow + it * 8;   // 0..63
            float4 kv = *(const float4*)&Kg[(size_t)(t0 + r) * HD + lcol];
            Ks[(lcol + 0) * KS + r] = kv.x;
            Ks[(lcol + 1) * KS + r] = kv.y;
            Ks[(lcol + 2) * KS + r] = kv.z;
            Ks[(lcol + 3) * KS + r] = kv.w;
            float4 vv = *(const float4*)&Vg[(size_t)(t0 + r) * HD + lcol];
            *(float4*)&Vs[r * VS + lcol] = vv;
        }
        __syncthreads();

        // S = Qs^T Ks : 128 rows x 64 keys, reduction over HD=64
        float s[8][8];
#pragma unroll
        for (int i = 0; i < 8; i++)
#pragma unroll
            for (int j = 0; j < 8; j++) s[i][j] = 0.f;

#pragma unroll 4
        for (int d = 0; d < HD; d++) {
            float4 av0 = *(const float4*)&Qs[d * QS + ty * 8];
            float4 av1 = *(const float4*)&Qs[d * QS + ty * 8 + 4];
            float4 bv0 = *(const float4*)&Ks[d * KS + tx * 8];
            float4 bv1 = *(const float4*)&Ks[d * KS + tx * 8 + 4];
            float a[8] = {av0.x, av0.y, av0.z, av0.w, av1.x, av1.y, av1.z, av1.w};
            float b[8] = {bv0.x, bv0.y, bv0.z, bv0.w, bv1.x, bv1.y, bv1.z, bv1.w};
#pragma unroll
            for (int i = 0; i < 8; i++)
#pragma unroll
                for (int j = 0; j < 8; j++)
                    s[i][j] = fmaf(a[i], b[j], s[i][j]);
        }

        // Online softmax (base-2). Row reduction across the 8-thread tx group.
#pragma unroll
        for (int i = 0; i < 8; i++) {
            float mx = s[i][0];
#pragma unroll
            for (int j = 1; j < 8; j++) mx = fmaxf(mx, s[i][j]);
#pragma unroll
            for (int off = 4; off > 0; off >>= 1)
                mx = fmaxf(mx, __shfl_xor_sync(0xffffffffu, mx, off, 8));
            const float mnew = fmaxf(mrow[i], mx);
            const float corr = ex2(mrow[i] - mnew);
            float ps = 0.f;
#pragma unroll
            for (int j = 0; j < 8; j++) {
                const float p = ex2(s[i][j] - mnew);
                ps += p;
                s[i][j] = p;
            }
#pragma unroll
            for (int off = 4; off > 0; off >>= 1)
                ps += __shfl_xor_sync(0xffffffffu, ps, off, 8);
            lsum[i] = lsum[i] * corr + ps;
            mrow[i] = mnew;
#pragma unroll
            for (int j = 0; j < 8; j++) o[i][j] *= corr;
        }

        // Stage P transposed: Ps[key][row], float4 over rows.
#pragma unroll
        for (int j = 0; j < 8; j++) {
            float* p = &Ps[(tx * 8 + j) * PS + ty * 8];
            *(float4*)p       = make_float4(s[0][j], s[1][j], s[2][j], s[3][j]);
            *(float4*)(p + 4) = make_float4(s[4][j], s[5][j], s[6][j], s[7][j]);
        }
        __syncthreads();

        // O += P V : 128 rows x 64 dims, reduction over 64 keys
#pragma unroll 4
        for (int t = 0; t < BN; t++) {
            float4 pv0 = *(const float4*)&Ps[t * PS + ty * 8];
            float4 pv1 = *(const float4*)&Ps[t * PS + ty * 8 + 4];
            float4 vv0 = *(const float4*)&Vs[t * VS + tx * 8];
            float4 vv1 = *(const float4*)&Vs[t * VS + tx * 8 + 4];
            float p[8] = {pv0.x, pv0.y, pv0.z, pv0.w, pv1.x, pv1.y, pv1.z, pv1.w};
            float vb[8] = {vv0.x, vv0.y, vv0.z, vv0.w, vv1.x, vv1.y, vv1.z, vv1.w};
#pragma unroll
            for (int i = 0; i < 8; i++)
#pragma unroll
                for (int j = 0; j < 8; j++)
                    o[i][j] = fmaf(p[i], vb[j], o[i][j]);
        }
    }

    // Epilogue: normalize, write to [B,S,D] (re-interleave heads).
    const int b = bh >> 3;
    const int h = bh & (NH - 1);
#pragma unroll
    for (int i = 0; i < 8; i++) {
        const float inv = 1.0f / lsum[i];
        const int srow = s0 + ty * 8 + i;
        float* p = &g_A[((size_t)(b * SEQ) + srow) * DM + h * HD + tx * 8];
        *(float4*)p       = make_float4(o[i][0] * inv, o[i][1] * inv,
                                        o[i][2] * inv, o[i][3] * inv);
        *(float4*)(p + 4) = make_float4(o[i][4] * inv, o[i][5] * inv,
                                        o[i][6] * inv, o[i][7] * inv);
    }
}

// ---------------------------------------------------------------------------
// kernel_launch: 5 launches, default stream, graph-capturable.
// Input order: q,k,v,mask,Wq,bq,Wk,bk,Wv,bv,Wo,bo
// ---------------------------------------------------------------------------
extern "C" void kernel_launch(void* const* d_in, const int* in_sizes, int n_in,
                              void* d_out, int out_size)
{
    (void)in_sizes; (void)n_in; (void)out_size;
    const float* q  = (const float*)d_in[0];
    const float* k  = (const float*)d_in[1];
    const float* v  = (const float*)d_in[2];
    // d_in[3] = mask (int32) — a no-op in the reference math
    const float* Wq = (const float*)d_in[4];
    const float* bq = (const float*)d_in[5];
    const float* Wk = (const float*)d_in[6];
    const float* bk = (const float*)d_in[7];
    const float* Wv = (const float*)d_in[8];
    const float* bv = (const float*)d_in[9];
    const float* Wo = (const float*)d_in[10];
    const float* bo = (const float*)d_in[11];
    float* out = (float*)d_out;

    const dim3 pgrid(DM / 128, MROWS / 128);   // (4, 64)

    proj_kernel<0><<<pgrid, 256>>>(q, Wq, bq, nullptr);
    proj_kernel<1><<<pgrid, 256>>>(k, Wk, bk, nullptr);
    proj_kernel<2><<<pgrid, 256>>>(v, Wv, bv, nullptr);

    const int smem_bytes = (HD * (128 + 4) + HD * (64 + 4) +
                            64 * (HD + 4) + 64 * (128 + 4)) * (int)sizeof(float); // 102400
    cudaFuncSetAttribute(flash_kernel,
                         cudaFuncAttributeMaxDynamicSharedMemorySize, smem_bytes);
    flash_kernel<<<dim3(SEQ / 128, NB * NH), 128, smem_bytes>>>();

    proj_kernel<3><<<pgrid, 256>>>(nullptr, Wo, bo, out);
}